// round 9
// baseline (speedup 1.0000x reference)
#include <cuda_runtime.h>
#include <math.h>

#define T_SEQ 4096
#define DIM 1024
#define HEADS 16
#define KV_HEADS 4
#define HD 64
#define KV_DIM 256
#define QSCALE (0.125f * 1.44269504088896340736f)   // scale * log2(e)

// Scratch (allocation-free rule: __device__ globals)
__device__ float g_Qt[T_SEQ * DIM];                 // tf32 Q*QSCALE, paired cols
__device__ float g_att[T_SEQ * DIM];                // attention out, tf32 paired
__device__ float g_Kt[KV_HEADS * T_SEQ * HD];       // tf32 K, [kvh][t][d-paired]
__device__ float g_Vt[KV_HEADS * T_SEQ * HD];       // tf32 V, [kvh][d][t] natural
__device__ float g_xt[T_SEQ * DIM];                 // tf32 x, paired cols
__device__ float g_qwt[DIM * DIM];                  // tf32 weights, paired cols
__device__ float g_kwt[KV_DIM * DIM];
__device__ float g_vwt[KV_DIM * DIM];
__device__ float g_owt[DIM * DIM];

__device__ __forceinline__ unsigned f2tf(float x) {
    unsigned r;
    asm("cvt.rna.tf32.f32 %0, %1;" : "=r"(r) : "f"(x));
    return r;
}
__device__ __forceinline__ float f2tf_f(float x) {
    return __uint_as_float(f2tf(x));
}
__device__ __forceinline__ float ex2f(float x) {
    float y;
    asm("ex2.approx.ftz.f32 %0, %1;" : "=f"(y) : "f"(x));
    return y;
}

__device__ __forceinline__ void mma_tf32(float* c, const unsigned* a, const unsigned* b) {
    asm volatile(
        "mma.sync.aligned.m16n8k8.row.col.f32.tf32.tf32.f32 "
        "{%0,%1,%2,%3}, {%4,%5,%6,%7}, {%8,%9}, {%0,%1,%2,%3};\n"
        : "+f"(c[0]), "+f"(c[1]), "+f"(c[2]), "+f"(c[3])
        : "r"(a[0]), "r"(a[1]), "r"(a[2]), "r"(a[3]),
          "r"(b[0]), "r"(b[1]));
}

__device__ __host__ __forceinline__ int perm8(int j) {
    return ((j & 3) << 1) | (j >> 2);
}
__device__ __forceinline__ int colphys(int c) {
    return (c & ~7) | perm8(c & 7);
}

#define CP16(d, s) asm volatile("cp.async.cg.shared.global [%0], [%1], 16;" :: "r"(d), "l"(s))
#define CP_COMMIT() asm volatile("cp.async.commit_group;" ::: "memory")
#define CP_WAIT0() asm volatile("cp.async.wait_group 0;" ::: "memory")
#define CP_WAIT1() asm volatile("cp.async.wait_group 1;" ::: "memory")

// ---------------------------------------------------------------------------
// prep: f32 -> tf32 with intra-8 pairing {0,4,1,5,2,6,3,7}
// ---------------------------------------------------------------------------
__global__ void prep_pair(const float* __restrict__ src, float* __restrict__ dst,
                          int n8)
{
    int i = blockIdx.x * blockDim.x + threadIdx.x;
    if (i >= n8) return;
    const float* s = src + (size_t)i * 8;
    float4 v0 = *(const float4*)s;
    float4 v1 = *(const float4*)(s + 4);
    uint4 o0 = make_uint4(f2tf(v0.x), f2tf(v1.x), f2tf(v0.y), f2tf(v1.y));
    uint4 o1 = make_uint4(f2tf(v0.z), f2tf(v1.z), f2tf(v0.w), f2tf(v1.w));
    uint4* d = (uint4*)(dst + (size_t)i * 8);
    d[0] = o0; d[1] = o1;
}

// ---------------------------------------------------------------------------
// TF32 GEMM core, operands pre-converted (paired tf32): pure cp.async fills.
// C = A[M,1024] @ W[N,1024]^T + bias
// mode 0: f32 store, row stride DIM
// mode 1: Q: tf32(v*QSCALE) paired -> C
// mode 2: K: f32 kv-cache -> C + tf32 paired -> aux [kvh][t][d]
// mode 3: V: f32 kv-cache -> C + tf32 natural transposed -> aux [kvh][d][t]
// ---------------------------------------------------------------------------
struct GemmSmem { unsigned A[2][128][40]; unsigned W[2][128][40]; };

__device__ __forceinline__ void gemm_prefetch(const float* pa, const float* pw,
                                              GemmSmem& sm, int buf,
                                              int frow, int fcol, int k0)
{
    unsigned da = (unsigned)__cvta_generic_to_shared(&sm.A[buf][frow][fcol]);
    unsigned dw = (unsigned)__cvta_generic_to_shared(&sm.W[buf][frow][fcol]);
    const float* sa = pa + k0;
    const float* sw = pw + k0;
    #pragma unroll
    for (int j = 0; j < 4; j++) CP16(da + j * 16, sa + j * 4);
    #pragma unroll
    for (int j = 0; j < 4; j++) CP16(dw + j * 16, sw + j * 4);
    CP_COMMIT();
}

__device__ __forceinline__ void gemm_core(
    const float* __restrict__ At,     // paired tf32 [M][1024]
    const float* __restrict__ Wt,     // paired tf32 [N][1024]
    const float* __restrict__ bias,
    float* __restrict__ C,
    float* __restrict__ aux,
    int mb, int n_base, int mode, GemmSmem& sm)
{
    int tid  = threadIdx.x;
    int lane = tid & 31;
    int warp = tid >> 5;
    int wm = warp & 1;
    int wn = warp >> 1;
    int t = lane & 3;
    int g = lane >> 2;

    int frow = tid >> 1;          // 0..127
    int fcol = (tid & 1) * 16;    // 0 or 16
    const float* pa = At + (size_t)(mb + frow) * DIM + fcol;
    const float* pw = Wt + (size_t)(n_base + frow) * DIM + fcol;

    float acc[4][4][4];
    #pragma unroll
    for (int mt = 0; mt < 4; mt++)
        #pragma unroll
        for (int nt = 0; nt < 4; nt++)
            #pragma unroll
            for (int i = 0; i < 4; i++) acc[mt][nt][i] = 0.f;

    gemm_prefetch(pa, pw, sm, 0, frow, fcol, 0);

    int buf = 0;
    for (int k0 = 0; k0 < DIM; k0 += 32) {
        CP_WAIT0();
        __syncthreads();
        if (k0 + 32 < DIM)
            gemm_prefetch(pa, pw, sm, buf ^ 1, frow, fcol, k0 + 32);

        #pragma unroll
        for (int kt = 0; kt < 4; kt++) {
            unsigned a[4][4], b[4][2];
            #pragma unroll
            for (int mt = 0; mt < 4; mt++) {
                int row = wm * 64 + mt * 16 + g;
                uint2 v0 = *(uint2*)&sm.A[buf][row][kt * 8 + 2 * t];
                uint2 v1 = *(uint2*)&sm.A[buf][row + 8][kt * 8 + 2 * t];
                a[mt][0] = v0.x; a[mt][1] = v1.x; a[mt][2] = v0.y; a[mt][3] = v1.y;
            }
            #pragma unroll
            for (int nt = 0; nt < 4; nt++) {
                int bn = wn * 32 + nt * 8 + g;
                uint2 vb = *(uint2*)&sm.W[buf][bn][kt * 8 + 2 * t];
                b[nt][0] = vb.x; b[nt][1] = vb.y;
            }
            #pragma unroll
            for (int mt = 0; mt < 4; mt++)
                #pragma unroll
                for (int nt = 0; nt < 4; nt++)
                    mma_tf32(acc[mt][nt], a[mt], b[nt]);
        }
        buf ^= 1;
    }

    #pragma unroll
    for (int mt = 0; mt < 4; mt++) {
        int mm = mb + wm * 64 + mt * 16 + g;
        #pragma unroll
        for (int nt = 0; nt < 4; nt++) {
            int nn = n_base + wn * 32 + nt * 8 + 2 * t;
            float b0 = bias[nn], b1 = bias[nn + 1];
            float v00 = acc[mt][nt][0] + b0;
            float v01 = acc[mt][nt][1] + b1;
            float v10 = acc[mt][nt][2] + b0;
            float v11 = acc[mt][nt][3] + b1;

            if (mode == 0) {
                *(float2*)&C[(size_t)mm * DIM + nn]       = make_float2(v00, v01);
                *(float2*)&C[(size_t)(mm + 8) * DIM + nn] = make_float2(v10, v11);
            } else if (mode == 1) {
                int c0 = colphys(nn), c1 = colphys(nn + 1);
                C[(size_t)mm * DIM + c0]       = f2tf_f(v00 * QSCALE);
                C[(size_t)mm * DIM + c1]       = f2tf_f(v01 * QSCALE);
                C[(size_t)(mm + 8) * DIM + c0] = f2tf_f(v10 * QSCALE);
                C[(size_t)(mm + 8) * DIM + c1] = f2tf_f(v11 * QSCALE);
            } else if (mode == 2) {
                size_t base = (size_t)(nn >> 6) * (T_SEQ * HD) + (nn & 63);
                *(float2*)&C[base + (size_t)mm * HD]       = make_float2(v00, v01);
                *(float2*)&C[base + (size_t)(mm + 8) * HD] = make_float2(v10, v11);
                int d = nn & 63;
                int p0 = colphys(d), p1 = colphys(d + 1);
                size_t abase = (size_t)(nn >> 6) * (T_SEQ * HD);
                aux[abase + (size_t)mm * HD + p0]       = f2tf_f(v00);
                aux[abase + (size_t)mm * HD + p1]       = f2tf_f(v01);
                aux[abase + (size_t)(mm + 8) * HD + p0] = f2tf_f(v10);
                aux[abase + (size_t)(mm + 8) * HD + p1] = f2tf_f(v11);
            } else {
                size_t base = (size_t)(nn >> 6) * (T_SEQ * HD) + (nn & 63);
                *(float2*)&C[base + (size_t)mm * HD]       = make_float2(v00, v01);
                *(float2*)&C[base + (size_t)(mm + 8) * HD] = make_float2(v10, v11);
                int d = nn & 63;
                size_t abase = (size_t)(nn >> 6) * (HD * T_SEQ);
                aux[abase + (size_t)d * T_SEQ + mm]           = f2tf_f(v00);
                aux[abase + (size_t)(d + 1) * T_SEQ + mm]     = f2tf_f(v01);
                aux[abase + (size_t)d * T_SEQ + mm + 8]       = f2tf_f(v10);
                aux[abase + (size_t)(d + 1) * T_SEQ + mm + 8] = f2tf_f(v11);
            }
        }
    }
}

__global__ __launch_bounds__(256, 2)
void gemm_qkv(const float* __restrict__ xt,
              const float* __restrict__ qwt, const float* __restrict__ qb,
              const float* __restrict__ kwt, const float* __restrict__ kb,
              const float* __restrict__ vwt, const float* __restrict__ vb,
              float* __restrict__ qt,
              float* __restrict__ kc, float* __restrict__ ktt,
              float* __restrict__ vc, float* __restrict__ vtt)
{
    extern __shared__ GemmSmem sgm[];
    int bx = blockIdx.x;
    int mb = blockIdx.y * 128;
    if (bx < 8)
        gemm_core(xt, qwt, qb, qt, nullptr, mb, bx * 128, 1, sgm[0]);
    else if (bx < 10)
        gemm_core(xt, kwt, kb, kc, ktt, mb, (bx - 8) * 128, 2, sgm[0]);
    else
        gemm_core(xt, vwt, vb, vc, vtt, mb, (bx - 10) * 128, 3, sgm[0]);
}

__global__ __launch_bounds__(256, 2)
void gemm_o(const float* __restrict__ At, const float* __restrict__ wt,
            const float* __restrict__ b, float* __restrict__ C)
{
    extern __shared__ GemmSmem sgm[];
    gemm_core(At, wt, b, C, nullptr, blockIdx.y * 128, blockIdx.x * 128, 0, sgm[0]);
}

// ---------------------------------------------------------------------------
// TF32 flash attention, Br=128, O^T PV (P in-place as B operand), smem-staged
// coalesced epilogue writing tf32-paired output for gemm_o's cp.async fill.
// ---------------------------------------------------------------------------
__device__ __forceinline__ void load_kv_tile(float* Kbuf, float* Vbuf,
                                             const float* Kh, const float* Vh,
                                             int kstart, int tid)
{
    int row = tid >> 1;
    int cb = (tid & 1) * 32;
    const float* sK = Kh + (size_t)(kstart + row) * HD + cb;       // [key][d]
    const float* sV = Vh + (size_t)row * T_SEQ + kstart + cb;      // [d][seq]
    unsigned dK = (unsigned)__cvta_generic_to_shared(Kbuf + row * 72 + cb);
    unsigned dV = (unsigned)__cvta_generic_to_shared(Vbuf + row * 72 + cb);
    #pragma unroll
    for (int i = 0; i < 8; i++) CP16(dK + i * 16, sK + i * 4);
    #pragma unroll
    for (int i = 0; i < 8; i++) CP16(dV + i * 16, sV + i * 4);
    CP_COMMIT();
}

__global__ __launch_bounds__(128)
void flash_tf32(const float* __restrict__ Qt,
                const float* __restrict__ Kt,
                const float* __restrict__ Vt,
                float* __restrict__ O)
{
    extern __shared__ float smem[];
    float* Kf = smem;                 // [2][64 key][72 d]
    float* Vf = smem + 2 * 64 * 72;   // [2][64 d][72 seq]

    int tid  = threadIdx.x;
    int lane = tid & 31;
    int w = tid >> 5;
    int t = lane & 3;
    int g = lane >> 2;
    int qbi = (gridDim.x - 1) - blockIdx.x;   // heavy blocks first
    int h = blockIdx.y;
    int kvh = h >> 2;
    int qstart = qbi * 128;

    const float* Kh = Kt + (size_t)kvh * T_SEQ * HD;
    const float* Vh = Vt + (size_t)kvh * HD * T_SEQ;

    int r0g[2], r1g[2];
    #pragma unroll
    for (int smt = 0; smt < 2; smt++) {
        r0g[smt] = qstart + w * 32 + smt * 16 + g;
        r1g[smt] = r0g[smt] + 8;
    }

    unsigned qf[2][8][4];
    #pragma unroll
    for (int smt = 0; smt < 2; smt++)
        #pragma unroll
        for (int kt = 0; kt < 8; kt++) {
            uint2 v0 = *(const uint2*)&Qt[(size_t)r0g[smt] * DIM + h * HD + kt * 8 + 2 * t];
            uint2 v1 = *(const uint2*)&Qt[(size_t)r1g[smt] * DIM + h * HD + kt * 8 + 2 * t];
            qf[smt][kt][0] = v0.x; qf[smt][kt][1] = v1.x;
            qf[smt][kt][2] = v0.y; qf[smt][kt][3] = v1.y;
        }

    // O^T accumulators: oacc[mtD d-tile][ntP row-tile][4]
    float oacc[4][4][4];
    #pragma unroll
    for (int mtD = 0; mtD < 4; mtD++)
        #pragma unroll
        for (int ntP = 0; ntP < 4; ntP++)
            #pragma unroll
            for (int i = 0; i < 4; i++) oacc[mtD][ntP][i] = 0.f;

    float m0[2] = {-1e30f, -1e30f}, m1[2] = {-1e30f, -1e30f};
    float l0[2] = {0.f, 0.f}, l1[2] = {0.f, 0.f};

    int nkb = 2 * qbi + 2;
    load_kv_tile(Kf, Vf, Kh, Vh, 0, tid);

    for (int kb = 0; kb < nkb; kb++) {
        int b = kb & 1;
        if (kb + 1 < nkb) {
            load_kv_tile(Kf + (1 - b) * 64 * 72, Vf + (1 - b) * 64 * 72,
                         Kh, Vh, (kb + 1) * 64, tid);
            CP_WAIT1();
        } else {
            CP_WAIT0();
        }
        __syncthreads();

        const float* Kb = Kf + b * 64 * 72;
        const float* Vb = Vf + b * 64 * 72;
        int kstart = kb * 64;

        // ---- S = Q @ K^T ----
        float sacc[2][8][4];
        #pragma unroll
        for (int smt = 0; smt < 2; smt++)
            #pragma unroll
            for (int nt = 0; nt < 8; nt++)
                #pragma unroll
                for (int i = 0; i < 4; i++) sacc[smt][nt][i] = 0.f;

        #pragma unroll
        for (int kt = 0; kt < 8; kt++) {
            #pragma unroll
            for (int nt = 0; nt < 8; nt++) {
                uint2 bb = *(const uint2*)&Kb[(nt * 8 + g) * 72 + kt * 8 + 2 * t];
                mma_tf32(sacc[0][nt], qf[0][kt], (const unsigned*)&bb);
                mma_tf32(sacc[1][nt], qf[1][kt], (const unsigned*)&bb);
            }
        }

        // ---- causal mask ----
        if (kb >= 2 * qbi) {
            #pragma unroll
            for (int smt = 0; smt < 2; smt++)
                #pragma unroll
                for (int nt = 0; nt < 8; nt++) {
                    int c0 = kstart + nt * 8 + 2 * t;
                    int c1 = c0 + 1;
                    if (c0 > r0g[smt]) sacc[smt][nt][0] = -1e30f;
                    if (c1 > r0g[smt]) sacc[smt][nt][1] = -1e30f;
                    if (c0 > r1g[smt]) sacc[smt][nt][2] = -1e30f;
                    if (c1 > r1g[smt]) sacc[smt][nt][3] = -1e30f;
                }
        }

        // ---- online softmax stats ----
        float nm0[2], nm1[2], alpha0[2], alpha1[2];
        #pragma unroll
        for (int smt = 0; smt < 2; smt++) {
            float mx0 = -1e30f, mx1 = -1e30f;
            #pragma unroll
            for (int nt = 0; nt < 8; nt++) {
                mx0 = fmaxf(mx0, fmaxf(sacc[smt][nt][0], sacc[smt][nt][1]));
                mx1 = fmaxf(mx1, fmaxf(sacc[smt][nt][2], sacc[smt][nt][3]));
            }
            mx0 = fmaxf(mx0, __shfl_xor_sync(0xffffffffu, mx0, 1));
            mx0 = fmaxf(mx0, __shfl_xor_sync(0xffffffffu, mx0, 2));
            mx1 = fmaxf(mx1, __shfl_xor_sync(0xffffffffu, mx1, 1));
            mx1 = fmaxf(mx1, __shfl_xor_sync(0xffffffffu, mx1, 2));
            nm0[smt] = fmaxf(m0[smt], mx0);
            nm1[smt] = fmaxf(m1[smt], mx1);
            alpha0[smt] = ex2f(m0[smt] - nm0[smt]);
            alpha1[smt] = ex2f(m1[smt] - nm1[smt]);
            m0[smt] = nm0[smt]; m1[smt] = nm1[smt];
        }

        // ---- rescale O^T: alpha per q-row (n-dim) via broadcast ----
        #pragma unroll
        for (int ntP = 0; ntP < 4; ntP++) {
            int smt = ntP >> 1;
            float aval = (ntP & 1) ? alpha1[smt] : alpha0[smt];
            float av0 = __shfl_sync(0xffffffffu, aval, 8 * t);       // row 2t
            float av1 = __shfl_sync(0xffffffffu, aval, 8 * t + 4);   // row 2t+1
            #pragma unroll
            for (int mtD = 0; mtD < 4; mtD++) {
                oacc[mtD][ntP][0] *= av0;
                oacc[mtD][ntP][1] *= av1;
                oacc[mtD][ntP][2] *= av0;
                oacc[mtD][ntP][3] *= av1;
            }
        }

        // ---- exp + PV (P in-place as B operand; V as A operand) ----
        float rs0[2] = {0.f, 0.f}, rs1[2] = {0.f, 0.f};
        #pragma unroll
        for (int kt = 0; kt < 8; kt++) {
            #pragma unroll
            for (int smt = 0; smt < 2; smt++) {
                float p0 = ex2f(sacc[smt][kt][0] - nm0[smt]);
                float p1 = ex2f(sacc[smt][kt][1] - nm0[smt]);
                float p2 = ex2f(sacc[smt][kt][2] - nm1[smt]);
                float p3 = ex2f(sacc[smt][kt][3] - nm1[smt]);
                rs0[smt] += p0 + p1;
                rs1[smt] += p2 + p3;
                sacc[smt][kt][0] = f2tf_f(p0);
                sacc[smt][kt][1] = f2tf_f(p1);
                sacc[smt][kt][2] = f2tf_f(p2);
                sacc[smt][kt][3] = f2tf_f(p3);
            }
            #pragma unroll
            for (int mtD = 0; mtD < 4; mtD++) {
                uint2 u0 = *(const uint2*)&Vb[(mtD * 16 + g) * 72 + kt * 8 + 2 * t];
                uint2 u1 = *(const uint2*)&Vb[(mtD * 16 + 8 + g) * 72 + kt * 8 + 2 * t];
                unsigned a[4] = {u0.x, u1.x, u0.y, u1.y};
                mma_tf32(oacc[mtD][0], a, (const unsigned*)&sacc[0][kt][0]);
                mma_tf32(oacc[mtD][1], a, (const unsigned*)&sacc[0][kt][2]);
                mma_tf32(oacc[mtD][2], a, (const unsigned*)&sacc[1][kt][0]);
                mma_tf32(oacc[mtD][3], a, (const unsigned*)&sacc[1][kt][2]);
            }
        }
        #pragma unroll
        for (int smt = 0; smt < 2; smt++) {
            rs0[smt] += __shfl_xor_sync(0xffffffffu, rs0[smt], 1);
            rs0[smt] += __shfl_xor_sync(0xffffffffu, rs0[smt], 2);
            rs1[smt] += __shfl_xor_sync(0xffffffffu, rs1[smt], 1);
            rs1[smt] += __shfl_xor_sync(0xffffffffu, rs1[smt], 2);
            l0[smt] = l0[smt] * alpha0[smt] + rs0[smt];
            l1[smt] = l1[smt] * alpha1[smt] + rs1[smt];
        }

        __syncthreads();
    }

    // ---- epilogue: 1/l broadcast, stage tf32-paired O^T -> smem, coalesced
    float inv[4][2];
    #pragma unroll
    for (int ntP = 0; ntP < 4; ntP++) {
        int smt = ntP >> 1;
        float lval = (ntP & 1) ? l1[smt] : l0[smt];
        inv[ntP][0] = 1.f / __shfl_sync(0xffffffffu, lval, 8 * t);
        inv[ntP][1] = 1.f / __shfl_sync(0xffffffffu, lval, 8 * t + 4);
    }

    float* Os = smem;   // reuse K/V smem: [128 rows][68]
    #pragma unroll
    for (int mtD = 0; mtD < 4; mtD++) {
        int d0 = mtD * 16 + perm8(g);        // paired column position
        int d1 = d0 + 8;                     // perm8(g+8 within group) = +8
        #pragma unroll
        for (int ntP = 0; ntP < 4; ntP++) {
            int r0 = w * 32 + ntP * 8 + 2 * t;
            Os[(r0)     * 68 + d0] = f2tf_f(oacc[mtD][ntP][0] * inv[ntP][0]);
            Os[(r0 + 1) * 68 + d0] = f2tf_f(oacc[mtD][ntP][1] * inv[ntP][1]);
            Os[(r0)     * 68 + d1] = f2tf_f(oacc[mtD][ntP][2] * inv[ntP][0]);
            Os[(r0 + 1) * 68 + d1] = f2tf_f(oacc[mtD][ntP][3] * inv[ntP][1]);
        }
    }
    __syncthreads();
    {
        float* dst = &O[(size_t)(qstart + tid) * DIM + h * HD];
        const float* src = &Os[tid * 68];
        #pragma unroll
        for (int j = 0; j < 16; j++)
            *(float4*)&dst[j * 4] = *(const float4*)&src[j * 4];
    }
}

// ---------------------------------------------------------------------------
extern "C" void kernel_launch(void* const* d_in, const int* in_sizes, int n_in,
                              void* d_out, int out_size)
{
    const float* x   = (const float*)d_in[0];
    // d_in[1] = mask (causal) — analytic
    const float* q_w = (const float*)d_in[2];
    const float* q_b = (const float*)d_in[3];
    const float* k_w = (const float*)d_in[4];
    const float* k_b = (const float*)d_in[5];
    const float* v_w = (const float*)d_in[6];
    const float* v_b = (const float*)d_in[7];
    const float* o_w = (const float*)d_in[8];
    const float* o_b = (const float*)d_in[9];

    float* out  = (float*)d_out;
    float* kout = out + (size_t)T_SEQ * DIM;
    float* vout = kout + (size_t)KV_HEADS * T_SEQ * HD;

    float *qtbuf, *abuf, *ktbuf, *vtbuf, *xtbuf, *qwtbuf, *kwtbuf, *vwtbuf, *owtbuf;
    cudaGetSymbolAddress((void**)&qtbuf, g_Qt);
    cudaGetSymbolAddress((void**)&abuf,  g_att);
    cudaGetSymbolAddress((void**)&ktbuf, g_Kt);
    cudaGetSymbolAddress((void**)&vtbuf, g_Vt);
    cudaGetSymbolAddress((void**)&xtbuf, g_xt);
    cudaGetSymbolAddress((void**)&qwtbuf, g_qwt);
    cudaGetSymbolAddress((void**)&kwtbuf, g_kwt);
    cudaGetSymbolAddress((void**)&vwtbuf, g_vwt);
    cudaGetSymbolAddress((void**)&owtbuf, g_owt);

    const int gemm_smem  = (int)sizeof(GemmSmem);                 // 81920
    const int flash_smem = 2 * 2 * 64 * 72 * (int)sizeof(float);  // 73728
    cudaFuncSetAttribute(gemm_qkv, cudaFuncAttributeMaxDynamicSharedMemorySize, gemm_smem);
    cudaFuncSetAttribute(gemm_o,   cudaFuncAttributeMaxDynamicSharedMemorySize, gemm_smem);
    cudaFuncSetAttribute(flash_tf32, cudaFuncAttributeMaxDynamicSharedMemorySize, flash_smem);

    // prep: tf32+pair conversions (x and the 4 weight matrices)
    prep_pair<<<T_SEQ * DIM / 8 / 256, 256>>>(x,   xtbuf,  T_SEQ * DIM / 8);
    prep_pair<<<DIM * DIM / 8 / 256, 256>>>(q_w, qwtbuf, DIM * DIM / 8);
    prep_pair<<<KV_DIM * DIM / 8 / 256, 256>>>(k_w, kwtbuf, KV_DIM * DIM / 8);
    prep_pair<<<KV_DIM * DIM / 8 / 256, 256>>>(v_w, vwtbuf, KV_DIM * DIM / 8);
    prep_pair<<<DIM * DIM / 8 / 256, 256>>>(o_w, owtbuf, DIM * DIM / 8);

    // fused Q/K/V projections
    gemm_qkv<<<dim3(12, 32), 256, gemm_smem>>>(xtbuf, qwtbuf, q_b, kwtbuf, k_b,
                                               vwtbuf, v_b,
                                               qtbuf, kout, ktbuf, vout, vtbuf);
    // causal attention -> g_att (tf32 paired)
    flash_tf32<<<dim3(T_SEQ / 128, HEADS), 128, flash_smem>>>(qtbuf, ktbuf,
                                                              vtbuf, abuf);
    // output projection -> out
    gemm_o<<<dim3(8, 32), 256, gemm_smem>>>(abuf, owtbuf, o_b, out);
}

// round 10
// speedup vs baseline: 1.1184x; 1.1184x over previous
#include <cuda_runtime.h>
#include <math.h>

#define T_SEQ 4096
#define DIM 1024
#define HEADS 16
#define KV_HEADS 4
#define HD 64
#define KV_DIM 256
#define QSCALE (0.125f * 1.44269504088896340736f)   // scale * log2(e)

// Scratch (allocation-free rule: __device__ globals)
__device__ float g_Qt[T_SEQ * DIM];                 // tf32 Q*QSCALE, paired cols
__device__ float g_att[T_SEQ * DIM];                // attention output (f32)
__device__ float g_Kt[KV_HEADS * T_SEQ * HD];       // tf32 K, [kvh][t][d-paired]
__device__ float g_Vt[KV_HEADS * T_SEQ * HD];       // tf32 V, [kvh][d][t] natural

__device__ __forceinline__ unsigned f2tf(float x) {
    unsigned r;
    asm("cvt.rna.tf32.f32 %0, %1;" : "=r"(r) : "f"(x));
    return r;
}
__device__ __forceinline__ float f2tf_f(float x) {
    return __uint_as_float(f2tf(x));
}
__device__ __forceinline__ float ex2f(float x) {
    float y;
    asm("ex2.approx.ftz.f32 %0, %1;" : "=f"(y) : "f"(x));
    return y;
}

__device__ __forceinline__ void mma_tf32(float* c, const unsigned* a, const unsigned* b) {
    asm volatile(
        "mma.sync.aligned.m16n8k8.row.col.f32.tf32.tf32.f32 "
        "{%0,%1,%2,%3}, {%4,%5,%6,%7}, {%8,%9}, {%0,%1,%2,%3};\n"
        : "+f"(c[0]), "+f"(c[1]), "+f"(c[2]), "+f"(c[3])
        : "r"(a[0]), "r"(a[1]), "r"(a[2]), "r"(a[3]),
          "r"(b[0]), "r"(b[1]));
}

__device__ __host__ __forceinline__ int perm8(int j) {
    return ((j & 3) << 1) | (j >> 2);
}
__device__ __forceinline__ int colphys(int c) {
    return (c & ~7) | perm8(c & 7);
}

#define CP16(d, s) asm volatile("cp.async.cg.shared.global [%0], [%1], 16;" :: "r"(d), "l"(s))
#define CP_COMMIT() asm volatile("cp.async.commit_group;" ::: "memory")
#define CP_WAIT0() asm volatile("cp.async.wait_group 0;" ::: "memory")
#define CP_WAIT1() asm volatile("cp.async.wait_group 1;" ::: "memory")

// ---------------------------------------------------------------------------
// TF32 GEMM core (r6/r8 fill path: LDG + cvt + STS, double-buffered, reg
// prefetch) — measured best at 121.7us for QKV.
// mode 0: f32 store, row stride DIM
// mode 1: Q: tf32(v*QSCALE) paired -> C
// mode 2: K: f32 kv-cache -> C + tf32 paired -> aux [kvh][t][d]
// mode 3: V: f32 kv-cache -> C + tf32 NATURAL transposed -> aux [kvh][d][t]
// ---------------------------------------------------------------------------
struct GemmSmem { unsigned A[2][128][40]; unsigned W[2][128][40]; };

__device__ __forceinline__ void gemm_core(
    const float* __restrict__ A,
    const float* __restrict__ W,
    const float* __restrict__ bias,
    float* __restrict__ C,
    float* __restrict__ aux,
    int mb, int n_base, int mode, GemmSmem& sm)
{
    const int Kd = DIM;
    int tid  = threadIdx.x;
    int lane = tid & 31;
    int warp = tid >> 5;
    int wm = warp & 1;
    int wn = warp >> 1;
    int t = lane & 3;
    int g = lane >> 2;
    int frow = tid >> 2;          // 0..63
    int fgrp = tid & 3;           // col group of 8

    float acc[4][4][4];
    #pragma unroll
    for (int mt = 0; mt < 4; mt++)
        #pragma unroll
        for (int nt = 0; nt < 4; nt++)
            #pragma unroll
            for (int i = 0; i < 4; i++) acc[mt][nt][i] = 0.f;

    const float* pa0 = A + (size_t)(mb + frow) * Kd + fgrp * 8;
    const float* pa1 = pa0 + (size_t)64 * Kd;
    const float* pw0 = W + (size_t)(n_base + frow) * Kd + fgrp * 8;
    const float* pw1 = pw0 + (size_t)64 * Kd;

    float4 ra[4], rw[4];
    ra[0] = *(const float4*)pa0; ra[1] = *(const float4*)(pa0 + 4);
    ra[2] = *(const float4*)pa1; ra[3] = *(const float4*)(pa1 + 4);
    rw[0] = *(const float4*)pw0; rw[1] = *(const float4*)(pw0 + 4);
    rw[2] = *(const float4*)pw1; rw[3] = *(const float4*)(pw1 + 4);

    int buf = 0;
    for (int k0 = 0; k0 < Kd; k0 += 32) {
        {
            uint4 x0 = make_uint4(f2tf(ra[0].x), f2tf(ra[1].x), f2tf(ra[0].y), f2tf(ra[1].y));
            uint4 x1 = make_uint4(f2tf(ra[0].z), f2tf(ra[1].z), f2tf(ra[0].w), f2tf(ra[1].w));
            uint4 x2 = make_uint4(f2tf(ra[2].x), f2tf(ra[3].x), f2tf(ra[2].y), f2tf(ra[3].y));
            uint4 x3 = make_uint4(f2tf(ra[2].z), f2tf(ra[3].z), f2tf(ra[2].w), f2tf(ra[3].w));
            *(uint4*)&sm.A[buf][frow][fgrp * 8]          = x0;
            *(uint4*)&sm.A[buf][frow][fgrp * 8 + 4]      = x1;
            *(uint4*)&sm.A[buf][frow + 64][fgrp * 8]     = x2;
            *(uint4*)&sm.A[buf][frow + 64][fgrp * 8 + 4] = x3;
            uint4 y0 = make_uint4(f2tf(rw[0].x), f2tf(rw[1].x), f2tf(rw[0].y), f2tf(rw[1].y));
            uint4 y1 = make_uint4(f2tf(rw[0].z), f2tf(rw[1].z), f2tf(rw[0].w), f2tf(rw[1].w));
            uint4 y2 = make_uint4(f2tf(rw[2].x), f2tf(rw[3].x), f2tf(rw[2].y), f2tf(rw[3].y));
            uint4 y3 = make_uint4(f2tf(rw[2].z), f2tf(rw[3].z), f2tf(rw[2].w), f2tf(rw[3].w));
            *(uint4*)&sm.W[buf][frow][fgrp * 8]          = y0;
            *(uint4*)&sm.W[buf][frow][fgrp * 8 + 4]      = y1;
            *(uint4*)&sm.W[buf][frow + 64][fgrp * 8]     = y2;
            *(uint4*)&sm.W[buf][frow + 64][fgrp * 8 + 4] = y3;
        }
        __syncthreads();

        if (k0 + 32 < Kd) {
            int ko = k0 + 32;
            ra[0] = *(const float4*)(pa0 + ko); ra[1] = *(const float4*)(pa0 + ko + 4);
            ra[2] = *(const float4*)(pa1 + ko); ra[3] = *(const float4*)(pa1 + ko + 4);
            rw[0] = *(const float4*)(pw0 + ko); rw[1] = *(const float4*)(pw0 + ko + 4);
            rw[2] = *(const float4*)(pw1 + ko); rw[3] = *(const float4*)(pw1 + ko + 4);
        }

        #pragma unroll
        for (int kt = 0; kt < 4; kt++) {
            unsigned a[4][4], b[4][2];
            #pragma unroll
            for (int mt = 0; mt < 4; mt++) {
                int row = wm * 64 + mt * 16 + g;
                uint2 v0 = *(uint2*)&sm.A[buf][row][kt * 8 + 2 * t];
                uint2 v1 = *(uint2*)&sm.A[buf][row + 8][kt * 8 + 2 * t];
                a[mt][0] = v0.x; a[mt][1] = v1.x; a[mt][2] = v0.y; a[mt][3] = v1.y;
            }
            #pragma unroll
            for (int nt = 0; nt < 4; nt++) {
                int bn = wn * 32 + nt * 8 + g;
                uint2 vb = *(uint2*)&sm.W[buf][bn][kt * 8 + 2 * t];
                b[nt][0] = vb.x; b[nt][1] = vb.y;
            }
            #pragma unroll
            for (int mt = 0; mt < 4; mt++)
                #pragma unroll
                for (int nt = 0; nt < 4; nt++)
                    mma_tf32(acc[mt][nt], a[mt], b[nt]);
        }
        buf ^= 1;
    }

    #pragma unroll
    for (int mt = 0; mt < 4; mt++) {
        int mm = mb + wm * 64 + mt * 16 + g;
        #pragma unroll
        for (int nt = 0; nt < 4; nt++) {
            int nn = n_base + wn * 32 + nt * 8 + 2 * t;
            float b0 = bias[nn], b1 = bias[nn + 1];
            float v00 = acc[mt][nt][0] + b0;
            float v01 = acc[mt][nt][1] + b1;
            float v10 = acc[mt][nt][2] + b0;
            float v11 = acc[mt][nt][3] + b1;

            if (mode == 0) {
                *(float2*)&C[(size_t)mm * DIM + nn]       = make_float2(v00, v01);
                *(float2*)&C[(size_t)(mm + 8) * DIM + nn] = make_float2(v10, v11);
            } else if (mode == 1) {
                int c0 = colphys(nn), c1 = colphys(nn + 1);
                C[(size_t)mm * DIM + c0]       = f2tf_f(v00 * QSCALE);
                C[(size_t)mm * DIM + c1]       = f2tf_f(v01 * QSCALE);
                C[(size_t)(mm + 8) * DIM + c0] = f2tf_f(v10 * QSCALE);
                C[(size_t)(mm + 8) * DIM + c1] = f2tf_f(v11 * QSCALE);
            } else if (mode == 2) {
                size_t base = (size_t)(nn >> 6) * (T_SEQ * HD) + (nn & 63);
                *(float2*)&C[base + (size_t)mm * HD]       = make_float2(v00, v01);
                *(float2*)&C[base + (size_t)(mm + 8) * HD] = make_float2(v10, v11);
                int d = nn & 63;
                int p0 = colphys(d), p1 = colphys(d + 1);
                size_t abase = (size_t)(nn >> 6) * (T_SEQ * HD);
                aux[abase + (size_t)mm * HD + p0]       = f2tf_f(v00);
                aux[abase + (size_t)mm * HD + p1]       = f2tf_f(v01);
                aux[abase + (size_t)(mm + 8) * HD + p0] = f2tf_f(v10);
                aux[abase + (size_t)(mm + 8) * HD + p1] = f2tf_f(v11);
            } else {
                size_t base = (size_t)(nn >> 6) * (T_SEQ * HD) + (nn & 63);
                *(float2*)&C[base + (size_t)mm * HD]       = make_float2(v00, v01);
                *(float2*)&C[base + (size_t)(mm + 8) * HD] = make_float2(v10, v11);
                int d = nn & 63;
                size_t abase = (size_t)(nn >> 6) * (HD * T_SEQ);
                aux[abase + (size_t)d * T_SEQ + mm]           = f2tf_f(v00);
                aux[abase + (size_t)(d + 1) * T_SEQ + mm]     = f2tf_f(v01);
                aux[abase + (size_t)d * T_SEQ + mm + 8]       = f2tf_f(v10);
                aux[abase + (size_t)(d + 1) * T_SEQ + mm + 8] = f2tf_f(v11);
            }
        }
    }
}

__global__ __launch_bounds__(256, 2)
void gemm_qkv(const float* __restrict__ x,
              const float* __restrict__ qw, const float* __restrict__ qb,
              const float* __restrict__ kw, const float* __restrict__ kb,
              const float* __restrict__ vw, const float* __restrict__ vb,
              float* __restrict__ qt,
              float* __restrict__ kc, float* __restrict__ ktt,
              float* __restrict__ vc, float* __restrict__ vtt)
{
    extern __shared__ GemmSmem sgm[];
    int bx = blockIdx.x;
    int mb = blockIdx.y * 128;
    if (bx < 8)
        gemm_core(x, qw, qb, qt, nullptr, mb, bx * 128, 1, sgm[0]);
    else if (bx < 10)
        gemm_core(x, kw, kb, kc, ktt, mb, (bx - 8) * 128, 2, sgm[0]);
    else
        gemm_core(x, vw, vb, vc, vtt, mb, (bx - 10) * 128, 3, sgm[0]);
}

__global__ __launch_bounds__(256, 2)
void gemm_o(const float* __restrict__ A, const float* __restrict__ w,
            const float* __restrict__ b, float* __restrict__ C)
{
    extern __shared__ GemmSmem sgm[];
    gemm_core(A, w, b, C, nullptr, blockIdx.y * 128, blockIdx.x * 128, 0, sgm[0]);
}

// ---------------------------------------------------------------------------
// TF32 flash attention, Br=128, O^T PV (P in-place as B operand), smem-staged
// coalesced f32 epilogue. P fed to MMA WITHOUT explicit tf32 cvt (HW reads
// top 19 bits -> truncation rounding; removes 64 CVTs from the hot loop).
// ---------------------------------------------------------------------------
__device__ __forceinline__ void load_kv_tile(float* Kbuf, float* Vbuf,
                                             const float* Kh, const float* Vh,
                                             int kstart, int tid)
{
    int row = tid >> 1;
    int cb = (tid & 1) * 32;
    const float* sK = Kh + (size_t)(kstart + row) * HD + cb;       // [key][d]
    const float* sV = Vh + (size_t)row * T_SEQ + kstart + cb;      // [d][seq]
    unsigned dK = (unsigned)__cvta_generic_to_shared(Kbuf + row * 72 + cb);
    unsigned dV = (unsigned)__cvta_generic_to_shared(Vbuf + row * 72 + cb);
    #pragma unroll
    for (int i = 0; i < 8; i++) CP16(dK + i * 16, sK + i * 4);
    #pragma unroll
    for (int i = 0; i < 8; i++) CP16(dV + i * 16, sV + i * 4);
    CP_COMMIT();
}

__global__ __launch_bounds__(128)
void flash_tf32(const float* __restrict__ Qt,
                const float* __restrict__ Kt,
                const float* __restrict__ Vt,
                float* __restrict__ O)
{
    extern __shared__ float smem[];
    float* Kf = smem;                 // [2][64 key][72 d]
    float* Vf = smem + 2 * 64 * 72;   // [2][64 d][72 seq]

    int tid  = threadIdx.x;
    int lane = tid & 31;
    int w = tid >> 5;
    int t = lane & 3;
    int g = lane >> 2;
    int qbi = (gridDim.x - 1) - blockIdx.x;   // heavy blocks first
    int h = blockIdx.y;
    int kvh = h >> 2;
    int qstart = qbi * 128;

    const float* Kh = Kt + (size_t)kvh * T_SEQ * HD;
    const float* Vh = Vt + (size_t)kvh * HD * T_SEQ;

    int r0g[2], r1g[2];
    #pragma unroll
    for (int smt = 0; smt < 2; smt++) {
        r0g[smt] = qstart + w * 32 + smt * 16 + g;
        r1g[smt] = r0g[smt] + 8;
    }

    unsigned qf[2][8][4];
    #pragma unroll
    for (int smt = 0; smt < 2; smt++)
        #pragma unroll
        for (int kt = 0; kt < 8; kt++) {
            uint2 v0 = *(const uint2*)&Qt[(size_t)r0g[smt] * DIM + h * HD + kt * 8 + 2 * t];
            uint2 v1 = *(const uint2*)&Qt[(size_t)r1g[smt] * DIM + h * HD + kt * 8 + 2 * t];
            qf[smt][kt][0] = v0.x; qf[smt][kt][1] = v1.x;
            qf[smt][kt][2] = v0.y; qf[smt][kt][3] = v1.y;
        }

    // O^T accumulators: oacc[mtD d-tile][ntP row-tile][4]
    float oacc[4][4][4];
    #pragma unroll
    for (int mtD = 0; mtD < 4; mtD++)
        #pragma unroll
        for (int ntP = 0; ntP < 4; ntP++)
            #pragma unroll
            for (int i = 0; i < 4; i++) oacc[mtD][ntP][i] = 0.f;

    float m0[2] = {-1e30f, -1e30f}, m1[2] = {-1e30f, -1e30f};
    float l0[2] = {0.f, 0.f}, l1[2] = {0.f, 0.f};

    int nkb = 2 * qbi + 2;
    load_kv_tile(Kf, Vf, Kh, Vh, 0, tid);

    for (int kb = 0; kb < nkb; kb++) {
        int b = kb & 1;
        if (kb + 1 < nkb) {
            load_kv_tile(Kf + (1 - b) * 64 * 72, Vf + (1 - b) * 64 * 72,
                         Kh, Vh, (kb + 1) * 64, tid);
            CP_WAIT1();
        } else {
            CP_WAIT0();
        }
        __syncthreads();

        const float* Kb = Kf + b * 64 * 72;
        const float* Vb = Vf + b * 64 * 72;
        int kstart = kb * 64;

        // ---- S = Q @ K^T ----
        float sacc[2][8][4];
        #pragma unroll
        for (int smt = 0; smt < 2; smt++)
            #pragma unroll
            for (int nt = 0; nt < 8; nt++)
                #pragma unroll
                for (int i = 0; i < 4; i++) sacc[smt][nt][i] = 0.f;

        #pragma unroll
        for (int kt = 0; kt < 8; kt++) {
            #pragma unroll
            for (int nt = 0; nt < 8; nt++) {
                uint2 bb = *(const uint2*)&Kb[(nt * 8 + g) * 72 + kt * 8 + 2 * t];
                mma_tf32(sacc[0][nt], qf[0][kt], (const unsigned*)&bb);
                mma_tf32(sacc[1][nt], qf[1][kt], (const unsigned*)&bb);
            }
        }

        // ---- causal mask ----
        if (kb >= 2 * qbi) {
            #pragma unroll
            for (int smt = 0; smt < 2; smt++)
                #pragma unroll
                for (int nt = 0; nt < 8; nt++) {
                    int c0 = kstart + nt * 8 + 2 * t;
                    int c1 = c0 + 1;
                    if (c0 > r0g[smt]) sacc[smt][nt][0] = -1e30f;
                    if (c1 > r0g[smt]) sacc[smt][nt][1] = -1e30f;
                    if (c0 > r1g[smt]) sacc[smt][nt][2] = -1e30f;
                    if (c1 > r1g[smt]) sacc[smt][nt][3] = -1e30f;
                }
        }

        // ---- online softmax stats ----
        float nm0[2], nm1[2], alpha0[2], alpha1[2];
        #pragma unroll
        for (int smt = 0; smt < 2; smt++) {
            float mx0 = -1e30f, mx1 = -1e30f;
            #pragma unroll
            for (int nt = 0; nt < 8; nt++) {
                mx0 = fmaxf(mx0, fmaxf(sacc[smt][nt][0], sacc[smt][nt][1]));
                mx1 = fmaxf(mx1, fmaxf(sacc[smt][nt][2], sacc[smt][nt][3]));
            }
            mx0 = fmaxf(mx0, __shfl_xor_sync(0xffffffffu, mx0, 1));
            mx0 = fmaxf(mx0, __shfl_xor_sync(0xffffffffu, mx0, 2));
            mx1 = fmaxf(mx1, __shfl_xor_sync(0xffffffffu, mx1, 1));
            mx1 = fmaxf(mx1, __shfl_xor_sync(0xffffffffu, mx1, 2));
            nm0[smt] = fmaxf(m0[smt], mx0);
            nm1[smt] = fmaxf(m1[smt], mx1);
            alpha0[smt] = ex2f(m0[smt] - nm0[smt]);
            alpha1[smt] = ex2f(m1[smt] - nm1[smt]);
            m0[smt] = nm0[smt]; m1[smt] = nm1[smt];
        }

        // ---- rescale O^T: alpha per q-row (n-dim) via broadcast ----
        #pragma unroll
        for (int ntP = 0; ntP < 4; ntP++) {
            int smt = ntP >> 1;
            float aval = (ntP & 1) ? alpha1[smt] : alpha0[smt];
            float av0 = __shfl_sync(0xffffffffu, aval, 8 * t);       // row 2t
            float av1 = __shfl_sync(0xffffffffu, aval, 8 * t + 4);   // row 2t+1
            #pragma unroll
            for (int mtD = 0; mtD < 4; mtD++) {
                oacc[mtD][ntP][0] *= av0;
                oacc[mtD][ntP][1] *= av1;
                oacc[mtD][ntP][2] *= av0;
                oacc[mtD][ntP][3] *= av1;
            }
        }

        // ---- exp + PV (P in-place as B operand, NO cvt; V as A operand) ----
        float rs0[2] = {0.f, 0.f}, rs1[2] = {0.f, 0.f};
        #pragma unroll
        for (int kt = 0; kt < 8; kt++) {
            #pragma unroll
            for (int smt = 0; smt < 2; smt++) {
                float p0 = ex2f(sacc[smt][kt][0] - nm0[smt]);
                float p1 = ex2f(sacc[smt][kt][1] - nm0[smt]);
                float p2 = ex2f(sacc[smt][kt][2] - nm1[smt]);
                float p3 = ex2f(sacc[smt][kt][3] - nm1[smt]);
                rs0[smt] += p0 + p1;
                rs1[smt] += p2 + p3;
                sacc[smt][kt][0] = p0;   // raw f32 bits; MMA reads top 19
                sacc[smt][kt][1] = p1;
                sacc[smt][kt][2] = p2;
                sacc[smt][kt][3] = p3;
            }
            #pragma unroll
            for (int mtD = 0; mtD < 4; mtD++) {
                uint2 u0 = *(const uint2*)&Vb[(mtD * 16 + g) * 72 + kt * 8 + 2 * t];
                uint2 u1 = *(const uint2*)&Vb[(mtD * 16 + 8 + g) * 72 + kt * 8 + 2 * t];
                unsigned a[4] = {u0.x, u1.x, u0.y, u1.y};
                mma_tf32(oacc[mtD][0], a, (const unsigned*)&sacc[0][kt][0]);
                mma_tf32(oacc[mtD][1], a, (const unsigned*)&sacc[0][kt][2]);
                mma_tf32(oacc[mtD][2], a, (const unsigned*)&sacc[1][kt][0]);
                mma_tf32(oacc[mtD][3], a, (const unsigned*)&sacc[1][kt][2]);
            }
        }
        #pragma unroll
        for (int smt = 0; smt < 2; smt++) {
            rs0[smt] += __shfl_xor_sync(0xffffffffu, rs0[smt], 1);
            rs0[smt] += __shfl_xor_sync(0xffffffffu, rs0[smt], 2);
            rs1[smt] += __shfl_xor_sync(0xffffffffu, rs1[smt], 1);
            rs1[smt] += __shfl_xor_sync(0xffffffffu, rs1[smt], 2);
            l0[smt] = l0[smt] * alpha0[smt] + rs0[smt];
            l1[smt] = l1[smt] * alpha1[smt] + rs1[smt];
        }

        __syncthreads();
    }

    // ---- epilogue: 1/l broadcast, stage O^T -> smem, coalesced f32 stores
    float inv[4][2];
    #pragma unroll
    for (int ntP = 0; ntP < 4; ntP++) {
        int smt = ntP >> 1;
        float lval = (ntP & 1) ? l1[smt] : l0[smt];
        inv[ntP][0] = 1.f / __shfl_sync(0xffffffffu, lval, 8 * t);
        inv[ntP][1] = 1.f / __shfl_sync(0xffffffffu, lval, 8 * t + 4);
    }

    float* Os = smem;   // reuse K/V smem: [128 rows][68]
    #pragma unroll
    for (int mtD = 0; mtD < 4; mtD++) {
        int d0 = mtD * 16 + g;
        int d1 = d0 + 8;
        #pragma unroll
        for (int ntP = 0; ntP < 4; ntP++) {
            int r0 = w * 32 + ntP * 8 + 2 * t;
            Os[(r0)     * 68 + d0] = oacc[mtD][ntP][0] * inv[ntP][0];
            Os[(r0 + 1) * 68 + d0] = oacc[mtD][ntP][1] * inv[ntP][1];
            Os[(r0)     * 68 + d1] = oacc[mtD][ntP][2] * inv[ntP][0];
            Os[(r0 + 1) * 68 + d1] = oacc[mtD][ntP][3] * inv[ntP][1];
        }
    }
    __syncthreads();
    {
        float* dst = &O[(size_t)(qstart + tid) * DIM + h * HD];
        const float* src = &Os[tid * 68];
        #pragma unroll
        for (int j = 0; j < 16; j++)
            *(float4*)&dst[j * 4] = *(const float4*)&src[j * 4];
    }
}

// ---------------------------------------------------------------------------
extern "C" void kernel_launch(void* const* d_in, const int* in_sizes, int n_in,
                              void* d_out, int out_size)
{
    const float* x   = (const float*)d_in[0];
    // d_in[1] = mask (causal) — analytic
    const float* q_w = (const float*)d_in[2];
    const float* q_b = (const float*)d_in[3];
    const float* k_w = (const float*)d_in[4];
    const float* k_b = (const float*)d_in[5];
    const float* v_w = (const float*)d_in[6];
    const float* v_b = (const float*)d_in[7];
    const float* o_w = (const float*)d_in[8];
    const float* o_b = (const float*)d_in[9];

    float* out  = (float*)d_out;
    float* kout = out + (size_t)T_SEQ * DIM;
    float* vout = kout + (size_t)KV_HEADS * T_SEQ * HD;

    float *qtbuf, *abuf, *ktbuf, *vtbuf;
    cudaGetSymbolAddress((void**)&qtbuf, g_Qt);
    cudaGetSymbolAddress((void**)&abuf,  g_att);
    cudaGetSymbolAddress((void**)&ktbuf, g_Kt);
    cudaGetSymbolAddress((void**)&vtbuf, g_Vt);

    const int gemm_smem  = (int)sizeof(GemmSmem);                 // 81920
    const int flash_smem = 2 * 2 * 64 * 72 * (int)sizeof(float);  // 73728
    cudaFuncSetAttribute(gemm_qkv, cudaFuncAttributeMaxDynamicSharedMemorySize, gemm_smem);
    cudaFuncSetAttribute(gemm_o,   cudaFuncAttributeMaxDynamicSharedMemorySize, gemm_smem);
    cudaFuncSetAttribute(flash_tf32, cudaFuncAttributeMaxDynamicSharedMemorySize, flash_smem);

    // fused Q/K/V projections
    gemm_qkv<<<dim3(12, 32), 256, gemm_smem>>>(x, q_w, q_b, k_w, k_b, v_w, v_b,
                                               qtbuf, kout, ktbuf, vout, vtbuf);
    // causal attention -> g_att (f32)
    flash_tf32<<<dim3(T_SEQ / 128, HEADS), 128, flash_smem>>>(qtbuf, ktbuf,
                                                              vtbuf, abuf);
    // output projection -> out
    gemm_o<<<dim3(8, 32), 256, gemm_smem>>>(abuf, o_w, o_b, out);
}

// round 12
// speedup vs baseline: 1.1633x; 1.0401x over previous
#include <cuda_runtime.h>
#include <math.h>

#define T_SEQ 4096
#define DIM 1024
#define HEADS 16
#define KV_HEADS 4
#define HD 64
#define KV_DIM 256
#define QSCALE (0.125f * 1.44269504088896340736f)   // scale * log2(e)

// Scratch (allocation-free rule: __device__ globals)
__device__ float g_Qt[T_SEQ * DIM];                 // tf32 Q*QSCALE, paired cols
__device__ float g_att[T_SEQ * DIM];                // attention output (f32)
__device__ float g_Kt[KV_HEADS * T_SEQ * HD];       // tf32 K, [kvh][t][d-paired]
__device__ float g_Vt[KV_HEADS * T_SEQ * HD];       // tf32 V, [kvh][d][t] natural

__device__ __forceinline__ unsigned f2tf(float x) {
    unsigned r;
    asm("cvt.rna.tf32.f32 %0, %1;" : "=r"(r) : "f"(x));
    return r;
}
__device__ __forceinline__ float f2tf_f(float x) {
    return __uint_as_float(f2tf(x));
}
__device__ __forceinline__ float ex2f(float x) {
    float y;
    asm("ex2.approx.ftz.f32 %0, %1;" : "=f"(y) : "f"(x));
    return y;
}

__device__ __forceinline__ void mma_tf32(float* c, const unsigned* a, const unsigned* b) {
    asm volatile(
        "mma.sync.aligned.m16n8k8.row.col.f32.tf32.tf32.f32 "
        "{%0,%1,%2,%3}, {%4,%5,%6,%7}, {%8,%9}, {%0,%1,%2,%3};\n"
        : "+f"(c[0]), "+f"(c[1]), "+f"(c[2]), "+f"(c[3])
        : "r"(a[0]), "r"(a[1]), "r"(a[2]), "r"(a[3]),
          "r"(b[0]), "r"(b[1]));
}

__device__ __host__ __forceinline__ int perm8(int j) {
    return ((j & 3) << 1) | (j >> 2);
}
__device__ __forceinline__ int colphys(int c) {
    return (c & ~7) | perm8(c & 7);
}

#define CP16(d, s) asm volatile("cp.async.cg.shared.global [%0], [%1], 16;" :: "r"(d), "l"(s))
#define CP_COMMIT() asm volatile("cp.async.commit_group;" ::: "memory")
#define CP_WAIT0() asm volatile("cp.async.wait_group 0;" ::: "memory")
#define CP_WAIT1() asm volatile("cp.async.wait_group 1;" ::: "memory")

// ---------------------------------------------------------------------------
// TF32 GEMM core (r8/r10 fill path: LDG + cvt + STS, double-buffered, reg
// prefetch) — measured 121.5us for QKV.
// mode 0: f32 store, row stride DIM
// mode 1: Q: tf32(v*QSCALE) paired -> C
// mode 2: K: f32 kv-cache -> C + tf32 paired -> aux [kvh][t][d]
// mode 3: V: f32 kv-cache -> C + tf32 NATURAL transposed -> aux [kvh][d][t]
// ---------------------------------------------------------------------------
struct GemmSmem { unsigned A[2][128][40]; unsigned W[2][128][40]; };

__device__ __forceinline__ void gemm_core(
    const float* __restrict__ A,
    const float* __restrict__ W,
    const float* __restrict__ bias,
    float* __restrict__ C,
    float* __restrict__ aux,
    int mb, int n_base, int mode, GemmSmem& sm)
{
    const int Kd = DIM;
    int tid  = threadIdx.x;
    int lane = tid & 31;
    int warp = tid >> 5;
    int wm = warp & 1;
    int wn = warp >> 1;
    int t = lane & 3;
    int g = lane >> 2;
    int frow = tid >> 2;          // 0..63
    int fgrp = tid & 3;           // col group of 8

    float acc[4][4][4];
    #pragma unroll
    for (int mt = 0; mt < 4; mt++)
        #pragma unroll
        for (int nt = 0; nt < 4; nt++)
            #pragma unroll
            for (int i = 0; i < 4; i++) acc[mt][nt][i] = 0.f;

    const float* pa0 = A + (size_t)(mb + frow) * Kd + fgrp * 8;
    const float* pa1 = pa0 + (size_t)64 * Kd;
    const float* pw0 = W + (size_t)(n_base + frow) * Kd + fgrp * 8;
    const float* pw1 = pw0 + (size_t)64 * Kd;

    float4 ra[4], rw[4];
    ra[0] = *(const float4*)pa0; ra[1] = *(const float4*)(pa0 + 4);
    ra[2] = *(const float4*)pa1; ra[3] = *(const float4*)(pa1 + 4);
    rw[0] = *(const float4*)pw0; rw[1] = *(const float4*)(pw0 + 4);
    rw[2] = *(const float4*)pw1; rw[3] = *(const float4*)(pw1 + 4);

    int buf = 0;
    for (int k0 = 0; k0 < Kd; k0 += 32) {
        {
            uint4 x0 = make_uint4(f2tf(ra[0].x), f2tf(ra[1].x), f2tf(ra[0].y), f2tf(ra[1].y));
            uint4 x1 = make_uint4(f2tf(ra[0].z), f2tf(ra[1].z), f2tf(ra[0].w), f2tf(ra[1].w));
            uint4 x2 = make_uint4(f2tf(ra[2].x), f2tf(ra[3].x), f2tf(ra[2].y), f2tf(ra[3].y));
            uint4 x3 = make_uint4(f2tf(ra[2].z), f2tf(ra[3].z), f2tf(ra[2].w), f2tf(ra[3].w));
            *(uint4*)&sm.A[buf][frow][fgrp * 8]          = x0;
            *(uint4*)&sm.A[buf][frow][fgrp * 8 + 4]      = x1;
            *(uint4*)&sm.A[buf][frow + 64][fgrp * 8]     = x2;
            *(uint4*)&sm.A[buf][frow + 64][fgrp * 8 + 4] = x3;
            uint4 y0 = make_uint4(f2tf(rw[0].x), f2tf(rw[1].x), f2tf(rw[0].y), f2tf(rw[1].y));
            uint4 y1 = make_uint4(f2tf(rw[0].z), f2tf(rw[1].z), f2tf(rw[0].w), f2tf(rw[1].w));
            uint4 y2 = make_uint4(f2tf(rw[2].x), f2tf(rw[3].x), f2tf(rw[2].y), f2tf(rw[3].y));
            uint4 y3 = make_uint4(f2tf(rw[2].z), f2tf(rw[3].z), f2tf(rw[2].w), f2tf(rw[3].w));
            *(uint4*)&sm.W[buf][frow][fgrp * 8]          = y0;
            *(uint4*)&sm.W[buf][frow][fgrp * 8 + 4]      = y1;
            *(uint4*)&sm.W[buf][frow + 64][fgrp * 8]     = y2;
            *(uint4*)&sm.W[buf][frow + 64][fgrp * 8 + 4] = y3;
        }
        __syncthreads();

        if (k0 + 32 < Kd) {
            int ko = k0 + 32;
            ra[0] = *(const float4*)(pa0 + ko); ra[1] = *(const float4*)(pa0 + ko + 4);
            ra[2] = *(const float4*)(pa1 + ko); ra[3] = *(const float4*)(pa1 + ko + 4);
            rw[0] = *(const float4*)(pw0 + ko); rw[1] = *(const float4*)(pw0 + ko + 4);
            rw[2] = *(const float4*)(pw1 + ko); rw[3] = *(const float4*)(pw1 + ko + 4);
        }

        #pragma unroll
        for (int kt = 0; kt < 4; kt++) {
            unsigned a[4][4], b[4][2];
            #pragma unroll
            for (int mt = 0; mt < 4; mt++) {
                int row = wm * 64 + mt * 16 + g;
                uint2 v0 = *(uint2*)&sm.A[buf][row][kt * 8 + 2 * t];
                uint2 v1 = *(uint2*)&sm.A[buf][row + 8][kt * 8 + 2 * t];
                a[mt][0] = v0.x; a[mt][1] = v1.x; a[mt][2] = v0.y; a[mt][3] = v1.y;
            }
            #pragma unroll
            for (int nt = 0; nt < 4; nt++) {
                int bn = wn * 32 + nt * 8 + g;
                uint2 vb = *(uint2*)&sm.W[buf][bn][kt * 8 + 2 * t];
                b[nt][0] = vb.x; b[nt][1] = vb.y;
            }
            #pragma unroll
            for (int mt = 0; mt < 4; mt++)
                #pragma unroll
                for (int nt = 0; nt < 4; nt++)
                    mma_tf32(acc[mt][nt], a[mt], b[nt]);
        }
        buf ^= 1;
    }

    #pragma unroll
    for (int mt = 0; mt < 4; mt++) {
        int mm = mb + wm * 64 + mt * 16 + g;
        #pragma unroll
        for (int nt = 0; nt < 4; nt++) {
            int nn = n_base + wn * 32 + nt * 8 + 2 * t;
            float b0 = bias[nn], b1 = bias[nn + 1];
            float v00 = acc[mt][nt][0] + b0;
            float v01 = acc[mt][nt][1] + b1;
            float v10 = acc[mt][nt][2] + b0;
            float v11 = acc[mt][nt][3] + b1;

            if (mode == 0) {
                *(float2*)&C[(size_t)mm * DIM + nn]       = make_float2(v00, v01);
                *(float2*)&C[(size_t)(mm + 8) * DIM + nn] = make_float2(v10, v11);
            } else if (mode == 1) {
                int c0 = colphys(nn), c1 = colphys(nn + 1);
                C[(size_t)mm * DIM + c0]       = f2tf_f(v00 * QSCALE);
                C[(size_t)mm * DIM + c1]       = f2tf_f(v01 * QSCALE);
                C[(size_t)(mm + 8) * DIM + c0] = f2tf_f(v10 * QSCALE);
                C[(size_t)(mm + 8) * DIM + c1] = f2tf_f(v11 * QSCALE);
            } else if (mode == 2) {
                size_t base = (size_t)(nn >> 6) * (T_SEQ * HD) + (nn & 63);
                *(float2*)&C[base + (size_t)mm * HD]       = make_float2(v00, v01);
                *(float2*)&C[base + (size_t)(mm + 8) * HD] = make_float2(v10, v11);
                int d = nn & 63;
                int p0 = colphys(d), p1 = colphys(d + 1);
                size_t abase = (size_t)(nn >> 6) * (T_SEQ * HD);
                aux[abase + (size_t)mm * HD + p0]       = f2tf_f(v00);
                aux[abase + (size_t)mm * HD + p1]       = f2tf_f(v01);
                aux[abase + (size_t)(mm + 8) * HD + p0] = f2tf_f(v10);
                aux[abase + (size_t)(mm + 8) * HD + p1] = f2tf_f(v11);
            } else {
                size_t base = (size_t)(nn >> 6) * (T_SEQ * HD) + (nn & 63);
                *(float2*)&C[base + (size_t)mm * HD]       = make_float2(v00, v01);
                *(float2*)&C[base + (size_t)(mm + 8) * HD] = make_float2(v10, v11);
                int d = nn & 63;
                size_t abase = (size_t)(nn >> 6) * (HD * T_SEQ);
                aux[abase + (size_t)d * T_SEQ + mm]           = f2tf_f(v00);
                aux[abase + (size_t)(d + 1) * T_SEQ + mm]     = f2tf_f(v01);
                aux[abase + (size_t)d * T_SEQ + mm + 8]       = f2tf_f(v10);
                aux[abase + (size_t)(d + 1) * T_SEQ + mm + 8] = f2tf_f(v11);
            }
        }
    }
}

__global__ __launch_bounds__(256, 2)
void gemm_qkv(const float* __restrict__ x,
              const float* __restrict__ qw, const float* __restrict__ qb,
              const float* __restrict__ kw, const float* __restrict__ kb,
              const float* __restrict__ vw, const float* __restrict__ vb,
              float* __restrict__ qt,
              float* __restrict__ kc, float* __restrict__ ktt,
              float* __restrict__ vc, float* __restrict__ vtt)
{
    extern __shared__ GemmSmem sgm[];
    int bx = blockIdx.x;
    int mb = blockIdx.y * 128;
    if (bx < 8)
        gemm_core(x, qw, qb, qt, nullptr, mb, bx * 128, 1, sgm[0]);
    else if (bx < 10)
        gemm_core(x, kw, kb, kc, ktt, mb, (bx - 8) * 128, 2, sgm[0]);
    else
        gemm_core(x, vw, vb, vc, vtt, mb, (bx - 10) * 128, 3, sgm[0]);
}

__global__ __launch_bounds__(256, 2)
void gemm_o(const float* __restrict__ A, const float* __restrict__ w,
            const float* __restrict__ b, float* __restrict__ C)
{
    extern __shared__ GemmSmem sgm[];
    gemm_core(A, w, b, C, nullptr, blockIdx.y * 128, blockIdx.x * 128, 0, sgm[0]);
}

// ---------------------------------------------------------------------------
// TF32 flash attention, Br=256 (8 warps x 32 q-rows), O^T PV (P in-place as
// B operand, no cvt), cp.async double-buffered K/V, coalesced epilogue.
// ---------------------------------------------------------------------------
__device__ __forceinline__ void load_kv_tile(float* Kbuf, float* Vbuf,
                                             const float* Kh, const float* Vh,
                                             int kstart, int tid)
{
    int row = tid >> 2;           // 0..63 (256 threads)
    int cb = (tid & 3) * 16;      // 0,16,32,48
    const float* sK = Kh + (size_t)(kstart + row) * HD + cb;       // [key][d]
    const float* sV = Vh + (size_t)row * T_SEQ + kstart + cb;      // [d][seq]
    unsigned dK = (unsigned)__cvta_generic_to_shared(Kbuf + row * 72 + cb);
    unsigned dV = (unsigned)__cvta_generic_to_shared(Vbuf + row * 72 + cb);
    #pragma unroll
    for (int i = 0; i < 4; i++) CP16(dK + i * 16, sK + i * 4);
    #pragma unroll
    for (int i = 0; i < 4; i++) CP16(dV + i * 16, sV + i * 4);
    CP_COMMIT();
}

__global__ __launch_bounds__(256)
void flash_tf32(const float* __restrict__ Qt,
                const float* __restrict__ Kt,
                const float* __restrict__ Vt,
                float* __restrict__ O)
{
    extern __shared__ float smem[];
    float* Kf = smem;                 // [2][64 key][72 d]
    float* Vf = smem + 2 * 64 * 72;   // [2][64 d][72 seq]

    int tid  = threadIdx.x;
    int lane = tid & 31;
    int w = tid >> 5;                 // 0..7
    int t = lane & 3;
    int g = lane >> 2;
    int qbi = (gridDim.x - 1) - blockIdx.x;   // heavy blocks first, 0..15
    int h = blockIdx.y;
    int kvh = h >> 2;
    int qstart = qbi * 256;

    const float* Kh = Kt + (size_t)kvh * T_SEQ * HD;
    const float* Vh = Vt + (size_t)kvh * HD * T_SEQ;

    int r0g[2], r1g[2];
    #pragma unroll
    for (int smt = 0; smt < 2; smt++) {
        r0g[smt] = qstart + w * 32 + smt * 16 + g;
        r1g[smt] = r0g[smt] + 8;
    }

    unsigned qf[2][8][4];
    #pragma unroll
    for (int smt = 0; smt < 2; smt++)
        #pragma unroll
        for (int kt = 0; kt < 8; kt++) {
            uint2 v0 = *(const uint2*)&Qt[(size_t)r0g[smt] * DIM + h * HD + kt * 8 + 2 * t];
            uint2 v1 = *(const uint2*)&Qt[(size_t)r1g[smt] * DIM + h * HD + kt * 8 + 2 * t];
            qf[smt][kt][0] = v0.x; qf[smt][kt][1] = v1.x;
            qf[smt][kt][2] = v0.y; qf[smt][kt][3] = v1.y;
        }

    // O^T accumulators: oacc[mtD d-tile][ntP row-tile][4]
    float oacc[4][4][4];
    #pragma unroll
    for (int mtD = 0; mtD < 4; mtD++)
        #pragma unroll
        for (int ntP = 0; ntP < 4; ntP++)
            #pragma unroll
            for (int i = 0; i < 4; i++) oacc[mtD][ntP][i] = 0.f;

    float m0[2] = {-1e30f, -1e30f}, m1[2] = {-1e30f, -1e30f};
    float l0[2] = {0.f, 0.f}, l1[2] = {0.f, 0.f};

    int nkb = 4 * qbi + 4;
    load_kv_tile(Kf, Vf, Kh, Vh, 0, tid);

    for (int kb = 0; kb < nkb; kb++) {
        int b = kb & 1;
        if (kb + 1 < nkb) {
            load_kv_tile(Kf + (1 - b) * 64 * 72, Vf + (1 - b) * 64 * 72,
                         Kh, Vh, (kb + 1) * 64, tid);
            CP_WAIT1();
        } else {
            CP_WAIT0();
        }
        __syncthreads();

        const float* Kb = Kf + b * 64 * 72;
        const float* Vb = Vf + b * 64 * 72;
        int kstart = kb * 64;

        // ---- S = Q @ K^T ----
        float sacc[2][8][4];
        #pragma unroll
        for (int smt = 0; smt < 2; smt++)
            #pragma unroll
            for (int nt = 0; nt < 8; nt++)
                #pragma unroll
                for (int i = 0; i < 4; i++) sacc[smt][nt][i] = 0.f;

        #pragma unroll
        for (int kt = 0; kt < 8; kt++) {
            #pragma unroll
            for (int nt = 0; nt < 8; nt++) {
                uint2 bb = *(const uint2*)&Kb[(nt * 8 + g) * 72 + kt * 8 + 2 * t];
                mma_tf32(sacc[0][nt], qf[0][kt], (const unsigned*)&bb);
                mma_tf32(sacc[1][nt], qf[1][kt], (const unsigned*)&bb);
            }
        }

        // ---- causal mask (only tiles that can cross the diagonal) ----
        if (kb >= 4 * qbi) {
            #pragma unroll
            for (int smt = 0; smt < 2; smt++)
                #pragma unroll
                for (int nt = 0; nt < 8; nt++) {
                    int c0 = kstart + nt * 8 + 2 * t;
                    int c1 = c0 + 1;
                    if (c0 > r0g[smt]) sacc[smt][nt][0] = -1e30f;
                    if (c1 > r0g[smt]) sacc[smt][nt][1] = -1e30f;
                    if (c0 > r1g[smt]) sacc[smt][nt][2] = -1e30f;
                    if (c1 > r1g[smt]) sacc[smt][nt][3] = -1e30f;
                }
        }

        // ---- online softmax stats ----
        float nm0[2], nm1[2], alpha0[2], alpha1[2];
        #pragma unroll
        for (int smt = 0; smt < 2; smt++) {
            float mx0 = -1e30f, mx1 = -1e30f;
            #pragma unroll
            for (int nt = 0; nt < 8; nt++) {
                mx0 = fmaxf(mx0, fmaxf(sacc[smt][nt][0], sacc[smt][nt][1]));
                mx1 = fmaxf(mx1, fmaxf(sacc[smt][nt][2], sacc[smt][nt][3]));
            }
            mx0 = fmaxf(mx0, __shfl_xor_sync(0xffffffffu, mx0, 1));
            mx0 = fmaxf(mx0, __shfl_xor_sync(0xffffffffu, mx0, 2));
            mx1 = fmaxf(mx1, __shfl_xor_sync(0xffffffffu, mx1, 1));
            mx1 = fmaxf(mx1, __shfl_xor_sync(0xffffffffu, mx1, 2));
            nm0[smt] = fmaxf(m0[smt], mx0);
            nm1[smt] = fmaxf(m1[smt], mx1);
            alpha0[smt] = ex2f(m0[smt] - nm0[smt]);
            alpha1[smt] = ex2f(m1[smt] - nm1[smt]);
            m0[smt] = nm0[smt]; m1[smt] = nm1[smt];
        }

        // ---- rescale O^T: alpha per q-row (n-dim) via broadcast ----
        #pragma unroll
        for (int ntP = 0; ntP < 4; ntP++) {
            int smt = ntP >> 1;
            float aval = (ntP & 1) ? alpha1[smt] : alpha0[smt];
            float av0 = __shfl_sync(0xffffffffu, aval, 8 * t);       // row 2t
            float av1 = __shfl_sync(0xffffffffu, aval, 8 * t + 4);   // row 2t+1
            #pragma unroll
            for (int mtD = 0; mtD < 4; mtD++) {
                oacc[mtD][ntP][0] *= av0;
                oacc[mtD][ntP][1] *= av1;
                oacc[mtD][ntP][2] *= av0;
                oacc[mtD][ntP][3] *= av1;
            }
        }

        // ---- exp + PV (P in-place as B operand, no cvt; V as A operand) ----
        float rs0[2] = {0.f, 0.f}, rs1[2] = {0.f, 0.f};
        #pragma unroll
        for (int kt = 0; kt < 8; kt++) {
            #pragma unroll
            for (int smt = 0; smt < 2; smt++) {
                float p0 = ex2f(sacc[smt][kt][0] - nm0[smt]);
                float p1 = ex2f(sacc[smt][kt][1] - nm0[smt]);
                float p2 = ex2f(sacc[smt][kt][2] - nm1[smt]);
                float p3 = ex2f(sacc[smt][kt][3] - nm1[smt]);
                rs0[smt] += p0 + p1;
                rs1[smt] += p2 + p3;
                sacc[smt][kt][0] = p0;   // raw f32 bits; MMA reads top 19
                sacc[smt][kt][1] = p1;
                sacc[smt][kt][2] = p2;
                sacc[smt][kt][3] = p3;
            }
            #pragma unroll
            for (int mtD = 0; mtD < 4; mtD++) {
                uint2 u0 = *(const uint2*)&Vb[(mtD * 16 + g) * 72 + kt * 8 + 2 * t];
                uint2 u1 = *(const uint2*)&Vb[(mtD * 16 + 8 + g) * 72 + kt * 8 + 2 * t];
                unsigned a[4] = {u0.x, u1.x, u0.y, u1.y};
                mma_tf32(oacc[mtD][0], a, (const unsigned*)&sacc[0][kt][0]);
                mma_tf32(oacc[mtD][1], a, (const unsigned*)&sacc[0][kt][2]);
                mma_tf32(oacc[mtD][2], a, (const unsigned*)&sacc[1][kt][0]);
                mma_tf32(oacc[mtD][3], a, (const unsigned*)&sacc[1][kt][2]);
            }
        }
        #pragma unroll
        for (int smt = 0; smt < 2; smt++) {
            rs0[smt] += __shfl_xor_sync(0xffffffffu, rs0[smt], 1);
            rs0[smt] += __shfl_xor_sync(0xffffffffu, rs0[smt], 2);
            rs1[smt] += __shfl_xor_sync(0xffffffffu, rs1[smt], 1);
            rs1[smt] += __shfl_xor_sync(0xffffffffu, rs1[smt], 2);
            l0[smt] = l0[smt] * alpha0[smt] + rs0[smt];
            l1[smt] = l1[smt] * alpha1[smt] + rs1[smt];
        }

        __syncthreads();
    }

    // ---- epilogue: 1/l broadcast, stage O^T -> smem, coalesced f32 stores
    float inv[4][2];
    #pragma unroll
    for (int ntP = 0; ntP < 4; ntP++) {
        int smt = ntP >> 1;
        float lval = (ntP & 1) ? l1[smt] : l0[smt];
        inv[ntP][0] = 1.f / __shfl_sync(0xffffffffu, lval, 8 * t);
        inv[ntP][1] = 1.f / __shfl_sync(0xffffffffu, lval, 8 * t + 4);
    }

    float* Os = smem;   // reuse K/V smem: [256 rows][68]  (69632 B <= 73728)
    #pragma unroll
    for (int mtD = 0; mtD < 4; mtD++) {
        int d0 = mtD * 16 + g;
        int d1 = d0 + 8;
        #pragma unroll
        for (int ntP = 0; ntP < 4; ntP++) {
            int r0 = w * 32 + ntP * 8 + 2 * t;
            Os[(r0)     * 68 + d0] = oacc[mtD][ntP][0] * inv[ntP][0];
            Os[(r0 + 1) * 68 + d0] = oacc[mtD][ntP][1] * inv[ntP][1];
            Os[(r0)     * 68 + d1] = oacc[mtD][ntP][2] * inv[ntP][0];
            Os[(r0 + 1) * 68 + d1] = oacc[mtD][ntP][3] * inv[ntP][1];
        }
    }
    __syncthreads();
    {
        float* dst = &O[(size_t)(qstart + tid) * DIM + h * HD];
        const float* src = &Os[tid * 68];
        #pragma unroll
        for (int j = 0; j < 16; j++)
            *(float4*)&dst[j * 4] = *(const float4*)&src[j * 4];
    }
}

// ---------------------------------------------------------------------------
extern "C" void kernel_launch(void* const* d_in, const int* in_sizes, int n_in,
                              void* d_out, int out_size)
{
    const float* x   = (const float*)d_in[0];
    // d_in[1] = mask (causal) — analytic
    const float* q_w = (const float*)d_in[2];
    const float* q_b = (const float*)d_in[3];
    const float* k_w = (const float*)d_in[4];
    const float* k_b = (const float*)d_in[5];
    const float* v_w = (const float*)d_in[6];
    const float* v_b = (const float*)d_in[7];
    const float* o_w = (const float*)d_in[8];
    const float* o_b = (const float*)d_in[9];

    float* out  = (float*)d_out;
    float* kout = out + (size_t)T_SEQ * DIM;
    float* vout = kout + (size_t)KV_HEADS * T_SEQ * HD;

    float *qtbuf, *abuf, *ktbuf, *vtbuf;
    cudaGetSymbolAddress((void**)&qtbuf, g_Qt);
    cudaGetSymbolAddress((void**)&abuf,  g_att);
    cudaGetSymbolAddress((void**)&ktbuf, g_Kt);
    cudaGetSymbolAddress((void**)&vtbuf, g_Vt);

    const int gemm_smem  = (int)sizeof(GemmSmem);                 // 81920
    const int flash_smem = 2 * 2 * 64 * 72 * (int)sizeof(float);  // 73728
    cudaFuncSetAttribute(gemm_qkv, cudaFuncAttributeMaxDynamicSharedMemorySize, gemm_smem);
    cudaFuncSetAttribute(gemm_o,   cudaFuncAttributeMaxDynamicSharedMemorySize, gemm_smem);
    cudaFuncSetAttribute(flash_tf32, cudaFuncAttributeMaxDynamicSharedMemorySize, flash_smem);

    // fused Q/K/V projections
    gemm_qkv<<<dim3(12, 32), 256, gemm_smem>>>(x, q_w, q_b, k_w, k_b, v_w, v_b,
                                               qtbuf, kout, ktbuf, vout, vtbuf);
    // causal attention -> g_att (f32)  (Br=256: 16 q-blocks x 16 heads)
    flash_tf32<<<dim3(T_SEQ / 256, HEADS), 256, flash_smem>>>(qtbuf, ktbuf,
                                                              vtbuf, abuf);
    // output projection -> out
    gemm_o<<<dim3(8, 32), 256, gemm_smem>>>(abuf, o_w, o_b, out);
}